// round 6
// baseline (speedup 1.0000x reference)
#include <cuda_runtime.h>

#define K_B 2
#define K_R 5
#define K_N 1024
#define K_E 3
#define K_F 64
#define K_INRET 320
#define K_INTER 256
#define K_OUTRET 256
#define K_H1 128
#define K_HRET 320
#define K_CAT 384
#define INV_GAMMA 0.4f
#define SMS 68   // padded smem row stride (floats)
#define NN1 (K_N * K_N)
#define NF1 (K_N * K_F)
#define PHALF (2 * K_N * K_OUTRET)   // 524288

typedef unsigned long long ull;

__device__ __forceinline__ ull pack2(float lo, float hi) {
    ull r; asm("mov.b64 %0, {%1, %2};" : "=l"(r) : "f"(lo), "f"(hi)); return r;
}
__device__ __forceinline__ void fma2(ull& c, ull a, ull b) {
    asm("fma.rn.f32x2 %0, %1, %2, %3;" : "=l"(c) : "l"(a), "l"(b), "l"(c));
}
__device__ __forceinline__ float2 unpack2(ull v) {
    float lo, hi; asm("mov.b64 {%0, %1}, %2;" : "=f"(lo), "=f"(hi) : "l"(v));
    return make_float2(lo, hi);
}

// ---------------- device scratch ----------------
__device__ float g_P[2 * K_B * K_R * K_N * K_F];  // split-K partials (feats & ret)
__device__ float g_diff [K_B * K_R * K_N * K_F];
__device__ float g_h    [K_B * K_R * K_N * K_F];
__device__ float g_q [K_B * K_N * K_INTER];
__device__ float g_k [K_B * K_N * K_INTER];
__device__ float g_v [K_B * K_N * K_INTER];
__device__ float g_ms[K_B * K_N * K_N];
__device__ float g_cat[K_B * K_N * K_CAT];
__device__ float g_skipA[K_B * K_N * K_HRET];
__device__ float g_skipB[K_B * K_N * K_HRET];
__device__ float g_m1[K_B * K_N * K_H1];

// ---------------- R3-proven micro-kernel pieces ----------------
__device__ __forceinline__ void stage_q(float* S, int row, int q, float4 v) {
    S[(q * 4 + 0) * SMS + row] = v.x;
    S[(q * 4 + 1) * SMS + row] = v.y;
    S[(q * 4 + 2) * SMS + row] = v.z;
    S[(q * 4 + 3) * SMS + row] = v.w;
}

__device__ __forceinline__ void mma16(const float* As, const float* Bs,
                                      int tx, int ty, ull acc[2][4]) {
#pragma unroll
    for (int kk = 0; kk < 16; kk++) {
        ull a0 = *(const ull*)&As[kk * SMS + ty * 4];
        ull a1 = *(const ull*)&As[kk * SMS + ty * 4 + 2];
        float4 b4 = *(const float4*)&Bs[kk * SMS + tx * 4];
        ull b0 = pack2(b4.x, b4.x), b1 = pack2(b4.y, b4.y);
        ull b2 = pack2(b4.z, b4.z), b3 = pack2(b4.w, b4.w);
        fma2(acc[0][0], a0, b0); fma2(acc[0][1], a0, b1);
        fma2(acc[0][2], a0, b2); fma2(acc[0][3], a0, b3);
        fma2(acc[1][0], a1, b0); fma2(acc[1][1], a1, b1);
        fma2(acc[1][2], a1, b2); fma2(acc[1][3], a1, b3);
    }
}

// NT main loop: A rows of Az (ldA), B rows of Bz (ldB), K%16==0
template<bool ADD2>
__device__ __forceinline__ void loop_nt(const float* __restrict__ Az, int ldA,
                                        const float* __restrict__ A2z,
                                        const float* __restrict__ Bz, int ldB,
                                        int K, float* As, float* Bs, ull acc[2][4]) {
    int tid = threadIdx.x;
    int r_ = tid >> 2, q_ = tid & 3;
    int tx = tid & 15, ty = tid >> 4;
    float4 ar = *(const float4*)&Az[(long)r_ * ldA + q_ * 4];
    float4 br = *(const float4*)&Bz[(long)r_ * ldB + q_ * 4];
    float4 a2 = make_float4(0.f, 0.f, 0.f, 0.f);
    if (ADD2) a2 = *(const float4*)&A2z[(long)r_ * ldA + q_ * 4];
    for (int k0 = 0; k0 < K; k0 += 16) {
        if (ADD2) { ar.x += a2.x; ar.y += a2.y; ar.z += a2.z; ar.w += a2.w; }
        stage_q(As, r_, q_, ar);
        stage_q(Bs, r_, q_, br);
        __syncthreads();
        int kn = k0 + 16;
        if (kn < K) {
            ar = *(const float4*)&Az[(long)r_ * ldA + kn + q_ * 4];
            br = *(const float4*)&Bz[(long)r_ * ldB + kn + q_ * 4];
            if (ADD2) a2 = *(const float4*)&A2z[(long)r_ * ldA + kn + q_ * 4];
        }
        mma16(As, Bs, tx, ty, acc);
        __syncthreads();
    }
}

// NN main loop: B [K, ldB] row-major, already col-offset.
__device__ __forceinline__ void loop_nn(const float* __restrict__ Az, int ldA,
                                        const float* __restrict__ Bz, int ldB,
                                        int K, float* As, float* Bs, ull acc[2][4]) {
    int tid = threadIdx.x;
    int r_ = tid >> 2, q_ = tid & 3;
    int bk = tid >> 4, bc = tid & 15;
    int tx = tid & 15, ty = tid >> 4;
    float4 ar = *(const float4*)&Az[(long)r_ * ldA + q_ * 4];
    float4 br = *(const float4*)&Bz[(long)bk * ldB + bc * 4];
    for (int k0 = 0; k0 < K; k0 += 16) {
        stage_q(As, r_, q_, ar);
        *(float4*)&Bs[bk * SMS + bc * 4] = br;
        __syncthreads();
        int kn = k0 + 16;
        if (kn < K) {
            ar = *(const float4*)&Az[(long)r_ * ldA + kn + q_ * 4];
            br = *(const float4*)&Bz[(long)(kn + bk) * ldB + bc * 4];
        }
        mma16(As, Bs, tx, ty, acc);
        __syncthreads();
    }
}

// Epilogue: bias indexed by LOCAL column colb.
__device__ __forceinline__ void epi_store(float* Cz, int ldC, int row0, int colb,
                                          ull acc[2][4], const float* bias,
                                          float alpha, bool prelu) {
#pragma unroll
    for (int i = 0; i < 2; i++) {
        float r0[4], r1[4];
#pragma unroll
        for (int j = 0; j < 4; j++) {
            float2 p = unpack2(acc[i][j]); r0[j] = p.x; r1[j] = p.y;
            if (bias) { float bb = bias[colb + j]; r0[j] += bb; r1[j] += bb; }
            if (prelu) {
                r0[j] = (r0[j] >= 0.f) ? r0[j] : alpha * r0[j];
                r1[j] = (r1[j] >= 0.f) ? r1[j] : alpha * r1[j];
            }
        }
        int rr = row0 + 2 * i;
        *(float4*)&Cz[(long)rr * ldC + colb]       = *(float4*)r0;
        *(float4*)&Cz[(long)(rr + 1) * ldC + colb] = *(float4*)r1;
    }
}

// =============== generic NT 64x64 GEMM (fc / l2 / mlp1) ===============
template<bool ADD2>
__global__ void __launch_bounds__(256, 3) k_gemm64(
    const float* __restrict__ A, const float* __restrict__ A2,
    const float* __restrict__ B, const float* __restrict__ bias,
    float* __restrict__ C, int Nc, int K,
    long sAz, int ldA, long sBz, int ldB, int bMod, long sCz, int ldC,
    const float* __restrict__ alpha_ptr)
{
    __shared__ __align__(16) float As[16 * SMS];
    __shared__ __align__(16) float Bs[16 * SMS];
    int z = blockIdx.z;
    int m0 = blockIdx.y * 64, n0 = blockIdx.x * 64;
    int wz = z % bMod;
    const float* Az = A + (long)z * sAz + (long)m0 * ldA;
    const float* Bz = B + (long)wz * sBz + (long)n0 * ldB;
    float* Cz = C + (long)z * sCz;

    ull acc[2][4];
#pragma unroll
    for (int i = 0; i < 2; i++)
#pragma unroll
        for (int j = 0; j < 4; j++) acc[i][j] = 0ULL;
    loop_nt<ADD2>(Az, ldA, ADD2 ? (A2 + (long)z * sAz + (long)m0 * ldA) : nullptr,
                  Bz, ldB, K, As, Bs, acc);

    int tx = threadIdx.x & 15, ty = threadIdx.x >> 4;
    float alpha = alpha_ptr ? *alpha_ptr : 0.f;
    epi_store(Cz, ldC, m0 + ty * 4, n0 + tx * 4, acc,
              bias ? (bias + wz * Nc) : nullptr, alpha, alpha_ptr != nullptr);
}

// =============== feats: fused S, BOTH batches per block, split-K x2 ===============
// z in [0,10): r = z%5, chunk = z/5. T row-tile loaded once, both A[b] masks applied.
__global__ void __launch_bounds__(256, 3) k_feats(
    const float* __restrict__ Tm, const float* __restrict__ theta,
    const float* __restrict__ Ab, const float* __restrict__ H,
    float* __restrict__ P, int l)
{
    __shared__ __align__(16) float As0[16 * SMS], As1[16 * SMS];
    __shared__ __align__(16) float Bs0[16 * SMS], Bs1[16 * SMS];
    int z = blockIdx.z;
    int r = z % K_R, chunk = z / K_R;
    const float* T0 = Tm + (long)((l * K_R + r) * K_E) * NN1;
    const float* T1 = T0 + NN1;
    const float* T2 = T1 + NN1;
    const float* A0 = Ab + (long)r * NN1;
    const float* A1 = Ab + (long)(K_R + r) * NN1;
    const float* H0 = H + (long)r * NF1;
    const float* H1 = H + (long)(K_R + r) * NF1;
    float* C0 = P + (long)(chunk * (K_B * K_R) + r) * NF1;
    float* C1 = P + (long)(chunk * (K_B * K_R) + K_R + r) * NF1;
    float t0 = theta[(l * K_R + r) * K_E + 0];
    float t1 = theta[(l * K_R + r) * K_E + 1];
    float t2 = theta[(l * K_R + r) * K_E + 2];
    int m0 = blockIdx.y * 64;
    int Ks = chunk * (K_N / 2), Ke = Ks + K_N / 2;

    int tid = threadIdx.x;
    int r_ = tid >> 2, q_ = tid & 3;
    int bk = tid >> 4, bc = tid & 15;
    int tx = tid & 15, ty = tid >> 4;

    ull acc0[2][4], acc1[2][4];
#pragma unroll
    for (int i = 0; i < 2; i++)
#pragma unroll
        for (int j = 0; j < 4; j++) { acc0[i][j] = 0ULL; acc1[i][j] = 0ULL; }

    float4 tv0, tv1, tv2, av0, av1, hv0, hv1;
    {
        long off = (long)(m0 + r_) * K_N + Ks + q_ * 4;
        tv0 = *(const float4*)(T0 + off); tv1 = *(const float4*)(T1 + off);
        tv2 = *(const float4*)(T2 + off);
        av0 = *(const float4*)(A0 + off); av1 = *(const float4*)(A1 + off);
        hv0 = *(const float4*)&H0[(long)(Ks + bk) * K_F + bc * 4];
        hv1 = *(const float4*)&H1[(long)(Ks + bk) * K_F + bc * 4];
    }
    for (int k0 = Ks; k0 < Ke; k0 += 16) {
        float4 sv;
        sv.x = t0 * tv0.x + t1 * tv1.x + t2 * tv2.x;
        sv.y = t0 * tv0.y + t1 * tv1.y + t2 * tv2.y;
        sv.z = t0 * tv0.z + t1 * tv1.z + t2 * tv2.z;
        sv.w = t0 * tv0.w + t1 * tv1.w + t2 * tv2.w;
        float4 sa0 = make_float4(sv.x * av0.x, sv.y * av0.y, sv.z * av0.z, sv.w * av0.w);
        float4 sa1 = make_float4(sv.x * av1.x, sv.y * av1.y, sv.z * av1.z, sv.w * av1.w);
        stage_q(As0, r_, q_, sa0);
        stage_q(As1, r_, q_, sa1);
        *(float4*)&Bs0[bk * SMS + bc * 4] = hv0;
        *(float4*)&Bs1[bk * SMS + bc * 4] = hv1;
        __syncthreads();
        int kn = k0 + 16;
        if (kn < Ke) {
            long off = (long)(m0 + r_) * K_N + kn + q_ * 4;
            tv0 = *(const float4*)(T0 + off); tv1 = *(const float4*)(T1 + off);
            tv2 = *(const float4*)(T2 + off);
            av0 = *(const float4*)(A0 + off); av1 = *(const float4*)(A1 + off);
            hv0 = *(const float4*)&H0[(long)(kn + bk) * K_F + bc * 4];
            hv1 = *(const float4*)&H1[(long)(kn + bk) * K_F + bc * 4];
        }
        mma16(As0, Bs0, tx, ty, acc0);
        mma16(As1, Bs1, tx, ty, acc1);
        __syncthreads();
    }
    epi_store(C0, K_F, m0 + ty * 4, tx * 4, acc0, nullptr, 0.f, false);
    epi_store(C1, K_F, m0 + ty * 4, tx * 4, acc1, nullptr, 0.f, false);
}

// =============== fused q,k,v + ts projections (one launch, K=320) ===============
// grid (14, 32): x<12 -> qkv (which=x>>2, ntile=x&3); x>=12 -> ts (ntile=x-12).
__global__ void __launch_bounds__(256, 3) k_qkv_ts(
    const float* __restrict__ h, const float* __restrict__ skip,
    const float* __restrict__ qw, const float* __restrict__ kw, const float* __restrict__ vw,
    const float* __restrict__ qb, const float* __restrict__ kb, const float* __restrict__ vb,
    const float* __restrict__ l1w, const float* __restrict__ l1b,
    float* __restrict__ q, float* __restrict__ k, float* __restrict__ v,
    float* __restrict__ cat)
{
    __shared__ __align__(16) float As[16 * SMS];
    __shared__ __align__(16) float Bs[16 * SMS];
    int x = blockIdx.x;
    int m0 = blockIdx.y * 64;
    const float *A, *W, *bb;
    float* C; int ldC, n0;
    if (x < 12) {
        int which = x >> 2; n0 = (x & 3) * 64;
        A = h;
        W = ((which == 0) ? qw : (which == 1) ? kw : vw) + (long)n0 * K_INRET;
        bb = (which == 0) ? qb : (which == 1) ? kb : vb;
        C = (which == 0) ? q : (which == 1) ? k : v;
        ldC = K_INTER;
    } else {
        n0 = (x - 12) * 64;
        A = skip;
        W = l1w + (long)n0 * K_HRET;
        bb = l1b;
        C = cat + K_OUTRET;
        ldC = K_CAT;
    }
    ull acc[2][4];
#pragma unroll
    for (int i = 0; i < 2; i++)
#pragma unroll
        for (int j = 0; j < 4; j++) acc[i][j] = 0ULL;
    loop_nt<false>(A + (long)m0 * K_INRET, K_INRET, nullptr, W, K_INRET, K_INRET,
                   As, Bs, acc);
    int tx = threadIdx.x & 15, ty = threadIdx.x >> 4;
    epi_store(C, ldC, m0 + ty * 4, n0 + tx * 4, acc, bb, 0.f, false);
}

// =============== triangular masked scores ===============
__global__ void __launch_bounds__(256, 3) k_scores(
    const float* __restrict__ q, const float* __restrict__ k, float* __restrict__ ms)
{
    __shared__ __align__(16) float As[16 * SMS];
    __shared__ __align__(16) float Bs[16 * SMS];
    int i = blockIdx.x;
    int mt = (int)((sqrtf(8.f * i + 1.f) - 1.f) * 0.5f);
    while ((mt + 1) * (mt + 2) / 2 <= i) mt++;
    while (mt * (mt + 1) / 2 > i) mt--;
    int nt = i - mt * (mt + 1) / 2;
    int m0 = mt * 64, n0 = nt * 64;
    int z = blockIdx.y;
    const float* Az = q + (long)z * K_N * K_INTER + (long)m0 * K_INTER;
    const float* Bz = k + (long)z * K_N * K_INTER + (long)n0 * K_INTER;
    float* Cz = ms + (long)z * NN1;

    ull acc[2][4];
#pragma unroll
    for (int i2 = 0; i2 < 2; i2++)
#pragma unroll
        for (int j = 0; j < 4; j++) acc[i2][j] = 0ULL;
    loop_nt<false>(Az, K_INTER, nullptr, Bz, K_INTER, K_INTER, As, Bs, acc);

    int tx = threadIdx.x & 15, ty = threadIdx.x >> 4;
#pragma unroll
    for (int i2 = 0; i2 < 2; i2++) {
        int r0i = m0 + ty * 4 + 2 * i2;
        float r0[4], r1[4];
#pragma unroll
        for (int j = 0; j < 4; j++) {
            float2 p = unpack2(acc[i2][j]);
            int col = n0 + tx * 4 + j;
            r0[j] = (r0i > col)     ? INV_GAMMA * p.x : 0.f;
            r1[j] = (r0i + 1 > col) ? INV_GAMMA * p.y : 0.f;
        }
        *(float4*)&Cz[(long)r0i * K_N + n0 + tx * 4]       = *(float4*)r0;
        *(float4*)&Cz[(long)(r0i + 1) * K_N + n0 + tx * 4] = *(float4*)r1;
    }
}

// =============== ret = ms @ v, causal K-limit, split-K x2 -> partials ===============
// grid (4, 16, 4): z: b = z&1, chunk = z>>1.
__global__ void __launch_bounds__(256, 3) k_ret(
    const float* __restrict__ ms, const float* __restrict__ v, float* __restrict__ P)
{
    __shared__ __align__(16) float As[16 * SMS];
    __shared__ __align__(16) float Bs[16 * SMS];
    int z = blockIdx.z;
    int b = z & 1, chunk = z >> 1;
    int m0 = blockIdx.y * 64, n0 = blockIdx.x * 64;
    int Keff = m0 + 64;
    int half = Keff >> 1;            // multiple of 32
    int Ks = chunk ? half : 0;
    int Ke = chunk ? Keff : half;
    const float* Az = ms + (long)b * NN1 + (long)m0 * K_N + Ks;
    const float* Bz = v + (long)b * K_N * K_INTER + (long)Ks * K_INTER + n0;
    float* Cz = P + (long)chunk * PHALF + (long)b * K_N * K_OUTRET;

    ull acc[2][4];
#pragma unroll
    for (int i = 0; i < 2; i++)
#pragma unroll
        for (int j = 0; j < 4; j++) acc[i][j] = 0ULL;
    loop_nn(Az, K_N, Bz, K_INTER, Ke - Ks, As, Bs, acc);

    int tx = threadIdx.x & 15, ty = threadIdx.x >> 4;
    epi_store(Cz, K_OUTRET, m0 + ty * 4, n0 + tx * 4, acc, nullptr, 0.f, false);
}

// =============== eta = PReLU((P0+P1) @ rw^T + rb) -> cat[:, :256] ===============
__global__ void __launch_bounds__(256, 3) k_eta(
    const float* __restrict__ P, const float* __restrict__ rw,
    const float* __restrict__ rb, const float* __restrict__ a_ret,
    float* __restrict__ cat)
{
    __shared__ __align__(16) float As[16 * SMS];
    __shared__ __align__(16) float Bs[16 * SMS];
    int n0 = blockIdx.x * 64, m0 = blockIdx.y * 64;
    ull acc[2][4];
#pragma unroll
    for (int i = 0; i < 2; i++)
#pragma unroll
        for (int j = 0; j < 4; j++) acc[i][j] = 0ULL;
    loop_nt<true>(P + (long)m0 * K_OUTRET, K_OUTRET,
                  P + PHALF + (long)m0 * K_OUTRET,
                  rw + (long)n0 * K_INTER, K_INTER, K_INTER, As, Bs, acc);
    int tx = threadIdx.x & 15, ty = threadIdx.x >> 4;
    epi_store(cat, K_CAT, m0 + ty * 4, n0 + tx * 4, acc, rb, *a_ret, true);
}

// ---------------- conv over relations + PReLU ----------------
__global__ void k_conv(const float* __restrict__ diff, const float* __restrict__ cw,
                       const float* __restrict__ cb, const float* __restrict__ a1,
                       int l, float* __restrict__ u) {
    const int PQ = K_N * K_F / 4;
    int i = blockIdx.x * 256 + threadIdx.x;
    if (i >= K_B * K_R * PQ) return;
    int pq = i % PQ; int s = (i / PQ) % K_R; int b = i / (PQ * K_R);
    float bb = cb[l * K_R + s];
    float4 acc = make_float4(bb, bb, bb, bb);
    const float4* d4 = (const float4*)diff;
#pragma unroll
    for (int r2 = 0; r2 < K_R; r2++) {
        float w = cw[(l * K_R + s) * K_R + r2];
        float4 v = d4[(long)(b * K_R + r2) * PQ + pq];
        acc.x += w * v.x; acc.y += w * v.y; acc.z += w * v.z; acc.w += w * v.w;
    }
    float al = a1[l];
    acc.x = (acc.x >= 0.f) ? acc.x : al * acc.x;
    acc.y = (acc.y >= 0.f) ? acc.y : al * acc.y;
    acc.z = (acc.z >= 0.f) ? acc.z : al * acc.z;
    acc.w = (acc.w >= 0.f) ? acc.w : al * acc.w;
    ((float4*)u)[i] = acc;
}

// ---------------- initial skip transpose ----------------
__global__ void k_skip0(const float* __restrict__ x, float* __restrict__ sk) {
    int i = blockIdx.x * 256 + threadIdx.x;
    if (i >= K_B * K_N * K_R * K_F) return;
    int d = i % K_F;
    int r = (i / K_F) % K_R;
    int n = (i / (K_F * K_R)) % K_N;
    int b = i / (K_F * K_R * K_N);
    sk[i] = x[(((long)b * K_R + r) * K_N + n) * K_F + d];
}

// ---------------- final tiny GEMM: out[2048,2] ----------------
__global__ void k_mlp2(const float* __restrict__ m1, const float* __restrict__ w,
                       const float* __restrict__ b, float* __restrict__ out) {
    __shared__ float ws[2 * K_H1];
    int tid = threadIdx.x;
    if (tid < 2 * K_H1) ws[tid] = w[tid];
    __syncthreads();
    int row = blockIdx.x * 256 + tid;
    const float4* mr = (const float4*)(m1 + (long)row * K_H1);
    float s0 = 0.f, s1 = 0.f;
#pragma unroll
    for (int i = 0; i < K_H1 / 4; i++) {
        float4 v = mr[i];
        s0 += v.x * ws[i * 4] + v.y * ws[i * 4 + 1] + v.z * ws[i * 4 + 2] + v.w * ws[i * 4 + 3];
        s1 += v.x * ws[K_H1 + i * 4] + v.y * ws[K_H1 + i * 4 + 1]
            + v.z * ws[K_H1 + i * 4 + 2] + v.w * ws[K_H1 + i * 4 + 3];
    }
    out[(long)row * 2]     = s0 + b[0];
    out[(long)row * 2 + 1] = s1 + b[1];
}

// ---------------- host launcher ----------------
extern "C" void kernel_launch(void* const* d_in, const int* in_sizes, int n_in,
                              void* d_out, int out_size) {
    const float* x      = (const float*)d_in[0];
    const float* a      = (const float*)d_in[1];
    const float* T      = (const float*)d_in[2];
    const float* theta  = (const float*)d_in[3];
    const float* fc_w   = (const float*)d_in[4];
    const float* fc_b   = (const float*)d_in[5];
    const float* conv_w = (const float*)d_in[6];
    const float* conv_b = (const float*)d_in[7];
    const float* a0     = (const float*)d_in[8];
    const float* a1     = (const float*)d_in[9];
    const float* qw = (const float*)d_in[10]; const float* qb = (const float*)d_in[11];
    const float* kw = (const float*)d_in[12]; const float* kb = (const float*)d_in[13];
    const float* vw = (const float*)d_in[14]; const float* vb = (const float*)d_in[15];
    const float* rw = (const float*)d_in[16]; const float* rb = (const float*)d_in[17];
    const float* a_ret = (const float*)d_in[18];
    const float* l1w = (const float*)d_in[19]; const float* l1b = (const float*)d_in[20];
    const float* l2w = (const float*)d_in[21]; const float* l2b = (const float*)d_in[22];
    const float* m1w = (const float*)d_in[23]; const float* m1b = (const float*)d_in[24];
    const float* m2w = (const float*)d_in[25]; const float* m2b = (const float*)d_in[26];
    const float* a_mlp = (const float*)d_in[27];
    float* out = (float*)d_out;

    float *P, *diff, *h, *q, *k, *v, *ms, *cat, *skA, *skB, *m1;
    cudaGetSymbolAddress((void**)&P, g_P);
    cudaGetSymbolAddress((void**)&diff, g_diff);
    cudaGetSymbolAddress((void**)&h, g_h);
    cudaGetSymbolAddress((void**)&q, g_q);
    cudaGetSymbolAddress((void**)&k, g_k);
    cudaGetSymbolAddress((void**)&v, g_v);
    cudaGetSymbolAddress((void**)&ms, g_ms);
    cudaGetSymbolAddress((void**)&cat, g_cat);
    cudaGetSymbolAddress((void**)&skA, g_skipA);
    cudaGetSymbolAddress((void**)&skB, g_skipB);
    cudaGetSymbolAddress((void**)&m1, g_m1);

    const int M2 = K_B * K_N;  // 2048

    { int tot = K_B * K_N * K_R * K_F;
      k_skip0<<<(tot + 255) / 256, 256>>>(x, skA); }

    const float* hc = x;
    float* sin_ = skA;
    float* sout = skB;

    for (int l = 0; l < 2; l++) {
        // diffusion, fused S, both batches per block, split-K x2 (160 blocks)
        k_feats<<<dim3(1, K_N / 64, K_B * K_R), 256>>>(T, theta, a, hc, P, l);

        // fc + PReLU(a0), partial reduce fused into A staging (160 blocks)
        k_gemm64<true><<<dim3(1, K_N / 64, K_B * K_R), 256>>>(
            P, P + (long)K_B * K_R * NF1,
            fc_w + (long)l * K_R * K_F * K_F, fc_b + (long)l * K_R * K_F, diff,
            K_F, K_F, NF1, K_F, (long)K_F * K_F, K_F, K_R, NF1, K_F, a0 + l);

        { int tot = K_B * K_R * K_N * K_F / 4;
          k_conv<<<(tot + 255) / 256, 256>>>(diff, conv_w, conv_b, a1, l, h); }
        hc = h;

        // fused q,k,v + ts (448 blocks)
        k_qkv_ts<<<dim3(14, M2 / 64), 256>>>(
            h, sin_,
            qw + (long)l * K_INTER * K_INRET, kw + (long)l * K_INTER * K_INRET,
            vw + (long)l * K_INTER * K_INRET,
            qb + (long)l * K_INTER, kb + (long)l * K_INTER, vb + (long)l * K_INTER,
            l1w + (long)l * K_H1 * K_HRET, l1b + (long)l * K_H1,
            q, k, v, cat);

        // triangular masked scores (272 blocks)
        k_scores<<<dim3(136, 2), 256>>>(q, k, ms);

        // ret split-K x2 -> partials in P (256 blocks)
        k_ret<<<dim3(K_OUTRET / 64, K_N / 64, 4), 256>>>(ms, v, P);

        // eta with fused partial reduce (128 blocks)
        k_eta<<<dim3(K_OUTRET / 64, M2 / 64), 256>>>(
            P, rw + (long)l * K_OUTRET * K_INTER, rb + (long)l * K_OUTRET,
            a_ret + l, cat);

        // skip' = cat @ l2^T + l2_b (160 blocks)
        k_gemm64<false><<<dim3(K_HRET / 64, M2 / 64, 1), 256>>>(
            cat, nullptr, l2w + (long)l * K_HRET * K_CAT, l2b + (long)l * K_HRET, sout,
            K_HRET, K_CAT, 0, K_CAT, 0, K_CAT, 1, 0, K_HRET, nullptr);

        float* t0 = sin_; sin_ = sout; sout = t0;
    }

    // final MLP
    k_gemm64<false><<<dim3(K_H1 / 64, M2 / 64, 1), 256>>>(
        sin_, nullptr, m1w, m1b, m1,
        K_H1, K_HRET, 0, K_HRET, 0, K_HRET, 1, 0, K_H1, a_mlp);
    k_mlp2<<<M2 / 256, 256>>>(m1, m2w, m2b, out);
}

// round 7
// speedup vs baseline: 1.0247x; 1.0247x over previous
#include <cuda_runtime.h>

#define K_B 2
#define K_R 5
#define K_N 1024
#define K_E 3
#define K_F 64
#define K_INRET 320
#define K_INTER 256
#define K_OUTRET 256
#define K_H1 128
#define K_HRET 320
#define K_CAT 384
#define INV_GAMMA 0.4f
#define SMS 68    // 64-row smem stride
#define SMS8 132  // 128-row smem stride
#define NN1 (K_N * K_N)
#define NF1 (K_N * K_F)
#define PHALF (2 * K_N * K_OUTRET)

typedef unsigned long long ull;

__device__ __forceinline__ ull pack2(float lo, float hi) {
    ull r; asm("mov.b64 %0, {%1, %2};" : "=l"(r) : "f"(lo), "f"(hi)); return r;
}
__device__ __forceinline__ void fma2(ull& c, ull a, ull b) {
    asm("fma.rn.f32x2 %0, %1, %2, %3;" : "=l"(c) : "l"(a), "l"(b), "l"(c));
}
__device__ __forceinline__ float2 unpack2(ull v) {
    float lo, hi; asm("mov.b64 {%0, %1}, %2;" : "=f"(lo), "=f"(hi) : "l"(v));
    return make_float2(lo, hi);
}

// ---------------- device scratch ----------------
__device__ float g_P[2 * K_B * K_R * K_N * K_F];
__device__ float g_diff [K_B * K_R * K_N * K_F];
__device__ float g_h    [K_B * K_R * K_N * K_F];
__device__ float g_q [K_B * K_N * K_INTER];
__device__ float g_k [K_B * K_N * K_INTER];
__device__ float g_v [K_B * K_N * K_INTER];
__device__ float g_ms[K_B * K_N * K_N];
__device__ float g_cat[K_B * K_N * K_CAT];
__device__ float g_skipA[K_B * K_N * K_HRET];
__device__ float g_skipB[K_B * K_N * K_HRET];
__device__ float g_m1[K_B * K_N * K_H1];

// ---------------- 64-row micro-kernel (R3-proven) ----------------
__device__ __forceinline__ void stage_q(float* S, int row, int q, float4 v) {
    S[(q * 4 + 0) * SMS + row] = v.x;
    S[(q * 4 + 1) * SMS + row] = v.y;
    S[(q * 4 + 2) * SMS + row] = v.z;
    S[(q * 4 + 3) * SMS + row] = v.w;
}

__device__ __forceinline__ void mma16(const float* As, const float* Bs,
                                      int tx, int ty, ull acc[2][4]) {
#pragma unroll
    for (int kk = 0; kk < 16; kk++) {
        ull a0 = *(const ull*)&As[kk * SMS + ty * 4];
        ull a1 = *(const ull*)&As[kk * SMS + ty * 4 + 2];
        float4 b4 = *(const float4*)&Bs[kk * SMS + tx * 4];
        ull b0 = pack2(b4.x, b4.x), b1 = pack2(b4.y, b4.y);
        ull b2 = pack2(b4.z, b4.z), b3 = pack2(b4.w, b4.w);
        fma2(acc[0][0], a0, b0); fma2(acc[0][1], a0, b1);
        fma2(acc[0][2], a0, b2); fma2(acc[0][3], a0, b3);
        fma2(acc[1][0], a1, b0); fma2(acc[1][1], a1, b1);
        fma2(acc[1][2], a1, b2); fma2(acc[1][3], a1, b3);
    }
}

template<bool ADD2>
__device__ __forceinline__ void loop_nt(const float* __restrict__ Az, int ldA,
                                        const float* __restrict__ A2z,
                                        const float* __restrict__ Bz, int ldB,
                                        int K, float* As, float* Bs, ull acc[2][4]) {
    int tid = threadIdx.x;
    int r_ = tid >> 2, q_ = tid & 3;
    int tx = tid & 15, ty = tid >> 4;
    float4 ar = *(const float4*)&Az[(long)r_ * ldA + q_ * 4];
    float4 br = *(const float4*)&Bz[(long)r_ * ldB + q_ * 4];
    float4 a2 = make_float4(0.f, 0.f, 0.f, 0.f);
    if (ADD2) a2 = *(const float4*)&A2z[(long)r_ * ldA + q_ * 4];
    for (int k0 = 0; k0 < K; k0 += 16) {
        if (ADD2) { ar.x += a2.x; ar.y += a2.y; ar.z += a2.z; ar.w += a2.w; }
        stage_q(As, r_, q_, ar);
        stage_q(Bs, r_, q_, br);
        __syncthreads();
        int kn = k0 + 16;
        if (kn < K) {
            ar = *(const float4*)&Az[(long)r_ * ldA + kn + q_ * 4];
            br = *(const float4*)&Bz[(long)r_ * ldB + kn + q_ * 4];
            if (ADD2) a2 = *(const float4*)&A2z[(long)r_ * ldA + kn + q_ * 4];
        }
        mma16(As, Bs, tx, ty, acc);
        __syncthreads();
    }
}

__device__ __forceinline__ void loop_nn(const float* __restrict__ Az, int ldA,
                                        const float* __restrict__ Bz, int ldB,
                                        int K, float* As, float* Bs, ull acc[2][4]) {
    int tid = threadIdx.x;
    int r_ = tid >> 2, q_ = tid & 3;
    int bk = tid >> 4, bc = tid & 15;
    int tx = tid & 15, ty = tid >> 4;
    float4 ar = *(const float4*)&Az[(long)r_ * ldA + q_ * 4];
    float4 br = *(const float4*)&Bz[(long)bk * ldB + bc * 4];
    for (int k0 = 0; k0 < K; k0 += 16) {
        stage_q(As, r_, q_, ar);
        *(float4*)&Bs[bk * SMS + bc * 4] = br;
        __syncthreads();
        int kn = k0 + 16;
        if (kn < K) {
            ar = *(const float4*)&Az[(long)r_ * ldA + kn + q_ * 4];
            br = *(const float4*)&Bz[(long)(kn + bk) * ldB + bc * 4];
        }
        mma16(As, Bs, tx, ty, acc);
        __syncthreads();
    }
}

__device__ __forceinline__ void epi_store(float* Cz, int ldC, int row0, int colb,
                                          ull acc[2][4], const float* bias,
                                          float alpha, bool prelu) {
#pragma unroll
    for (int i = 0; i < 2; i++) {
        float r0[4], r1[4];
#pragma unroll
        for (int j = 0; j < 4; j++) {
            float2 p = unpack2(acc[i][j]); r0[j] = p.x; r1[j] = p.y;
            if (bias) { float bb = bias[colb + j]; r0[j] += bb; r1[j] += bb; }
            if (prelu) {
                r0[j] = (r0[j] >= 0.f) ? r0[j] : alpha * r0[j];
                r1[j] = (r1[j] >= 0.f) ? r1[j] : alpha * r1[j];
            }
        }
        int rr = row0 + 2 * i;
        *(float4*)&Cz[(long)rr * ldC + colb]       = *(float4*)r0;
        *(float4*)&Cz[(long)(rr + 1) * ldC + colb] = *(float4*)r1;
    }
}

// ---------------- 128-row micro-kernel (TM=8) ----------------
__device__ __forceinline__ void stage_q8(float* S, int row, int q, float4 v) {
    S[(q * 4 + 0) * SMS8 + row] = v.x;
    S[(q * 4 + 1) * SMS8 + row] = v.y;
    S[(q * 4 + 2) * SMS8 + row] = v.z;
    S[(q * 4 + 3) * SMS8 + row] = v.w;
}

__device__ __forceinline__ void mma16_8(const float* As, const float* Bs,
                                        int tx, int ty, ull acc[4][4]) {
#pragma unroll
    for (int kk = 0; kk < 16; kk++) {
        ull a[4];
#pragma unroll
        for (int i = 0; i < 4; i++) a[i] = *(const ull*)&As[kk * SMS8 + ty * 8 + 2 * i];
        float4 b4 = *(const float4*)&Bs[kk * SMS + tx * 4];
        ull b0 = pack2(b4.x, b4.x), b1 = pack2(b4.y, b4.y);
        ull b2 = pack2(b4.z, b4.z), b3 = pack2(b4.w, b4.w);
#pragma unroll
        for (int i = 0; i < 4; i++) {
            fma2(acc[i][0], a[i], b0); fma2(acc[i][1], a[i], b1);
            fma2(acc[i][2], a[i], b2); fma2(acc[i][3], a[i], b3);
        }
    }
}

// NT loop, A tile 128 rows, B tile 64 rows. K%16==0.
__device__ __forceinline__ void loop_nt8(const float* __restrict__ Az, int ldA,
                                         const float* __restrict__ Bz, int ldB,
                                         int K, float* As, float* Bs, ull acc[4][4]) {
    int tid = threadIdx.x;
    int r_ = tid >> 2, q_ = tid & 3;
    int tx = tid & 15, ty = tid >> 4;
    float4 a0 = *(const float4*)&Az[(long)r_ * ldA + q_ * 4];
    float4 a1 = *(const float4*)&Az[(long)(r_ + 64) * ldA + q_ * 4];
    float4 br = *(const float4*)&Bz[(long)r_ * ldB + q_ * 4];
    for (int k0 = 0; k0 < K; k0 += 16) {
        stage_q8(As, r_, q_, a0);
        stage_q8(As, r_ + 64, q_, a1);
        stage_q(Bs, r_, q_, br);
        __syncthreads();
        int kn = k0 + 16;
        if (kn < K) {
            a0 = *(const float4*)&Az[(long)r_ * ldA + kn + q_ * 4];
            a1 = *(const float4*)&Az[(long)(r_ + 64) * ldA + kn + q_ * 4];
            br = *(const float4*)&Bz[(long)r_ * ldB + kn + q_ * 4];
        }
        mma16_8(As, Bs, tx, ty, acc);
        __syncthreads();
    }
}

__device__ __forceinline__ void epi_store8(float* Cz, int ldC, int row0, int colb,
                                           ull acc[4][4], const float* bias,
                                           float alpha, bool prelu) {
#pragma unroll
    for (int i = 0; i < 4; i++) {
        float r0[4], r1[4];
#pragma unroll
        for (int j = 0; j < 4; j++) {
            float2 p = unpack2(acc[i][j]); r0[j] = p.x; r1[j] = p.y;
            if (bias) { float bb = bias[colb + j]; r0[j] += bb; r1[j] += bb; }
            if (prelu) {
                r0[j] = (r0[j] >= 0.f) ? r0[j] : alpha * r0[j];
                r1[j] = (r1[j] >= 0.f) ? r1[j] : alpha * r1[j];
            }
        }
        int rr = row0 + 2 * i;
        *(float4*)&Cz[(long)rr * ldC + colb]       = *(float4*)r0;
        *(float4*)&Cz[(long)(rr + 1) * ldC + colb] = *(float4*)r1;
    }
}

// =============== generic NT 64x64 GEMM (fc / l2 / mlp1) ===============
template<bool ADD2>
__global__ void __launch_bounds__(256, 3) k_gemm64(
    const float* __restrict__ A, const float* __restrict__ A2,
    const float* __restrict__ B, const float* __restrict__ bias,
    float* __restrict__ C, int Nc, int K,
    long sAz, int ldA, long sBz, int ldB, int bMod, long sCz, int ldC,
    const float* __restrict__ alpha_ptr)
{
    __shared__ __align__(16) float As[16 * SMS];
    __shared__ __align__(16) float Bs[16 * SMS];
    int z = blockIdx.z;
    int m0 = blockIdx.y * 64, n0 = blockIdx.x * 64;
    int wz = z % bMod;
    const float* Az = A + (long)z * sAz + (long)m0 * ldA;
    const float* Bz = B + (long)wz * sBz + (long)n0 * ldB;
    float* Cz = C + (long)z * sCz;

    ull acc[2][4];
#pragma unroll
    for (int i = 0; i < 2; i++)
#pragma unroll
        for (int j = 0; j < 4; j++) acc[i][j] = 0ULL;
    loop_nt<ADD2>(Az, ldA, ADD2 ? (A2 + (long)z * sAz + (long)m0 * ldA) : nullptr,
                  Bz, ldB, K, As, Bs, acc);

    int tx = threadIdx.x & 15, ty = threadIdx.x >> 4;
    float alpha = alpha_ptr ? *alpha_ptr : 0.f;
    epi_store(Cz, ldC, m0 + ty * 4, n0 + tx * 4, acc,
              bias ? (bias + wz * Nc) : nullptr, alpha, alpha_ptr != nullptr);
}

// =============== feats: fused S, BOTH batches per block, split-K x2 ===============
__global__ void __launch_bounds__(256, 3) k_feats(
    const float* __restrict__ Tm, const float* __restrict__ theta,
    const float* __restrict__ Ab, const float* __restrict__ H,
    float* __restrict__ P, int l)
{
    __shared__ __align__(16) float As0[16 * SMS], As1[16 * SMS];
    __shared__ __align__(16) float Bs0[16 * SMS], Bs1[16 * SMS];
    int z = blockIdx.z;
    int r = z % K_R, chunk = z / K_R;
    const float* T0 = Tm + (long)((l * K_R + r) * K_E) * NN1;
    const float* T1 = T0 + NN1;
    const float* T2 = T1 + NN1;
    const float* A0 = Ab + (long)r * NN1;
    const float* A1 = Ab + (long)(K_R + r) * NN1;
    const float* H0 = H + (long)r * NF1;
    const float* H1 = H + (long)(K_R + r) * NF1;
    float* C0 = P + (long)(chunk * (K_B * K_R) + r) * NF1;
    float* C1 = P + (long)(chunk * (K_B * K_R) + K_R + r) * NF1;
    float t0 = theta[(l * K_R + r) * K_E + 0];
    float t1 = theta[(l * K_R + r) * K_E + 1];
    float t2 = theta[(l * K_R + r) * K_E + 2];
    int m0 = blockIdx.y * 64;
    int Ks = chunk * (K_N / 2), Ke = Ks + K_N / 2;

    int tid = threadIdx.x;
    int r_ = tid >> 2, q_ = tid & 3;
    int bk = tid >> 4, bc = tid & 15;
    int tx = tid & 15, ty = tid >> 4;

    ull acc0[2][4], acc1[2][4];
#pragma unroll
    for (int i = 0; i < 2; i++)
#pragma unroll
        for (int j = 0; j < 4; j++) { acc0[i][j] = 0ULL; acc1[i][j] = 0ULL; }

    float4 tv0, tv1, tv2, av0, av1, hv0, hv1;
    {
        long off = (long)(m0 + r_) * K_N + Ks + q_ * 4;
        tv0 = *(const float4*)(T0 + off); tv1 = *(const float4*)(T1 + off);
        tv2 = *(const float4*)(T2 + off);
        av0 = *(const float4*)(A0 + off); av1 = *(const float4*)(A1 + off);
        hv0 = *(const float4*)&H0[(long)(Ks + bk) * K_F + bc * 4];
        hv1 = *(const float4*)&H1[(long)(Ks + bk) * K_F + bc * 4];
    }
    for (int k0 = Ks; k0 < Ke; k0 += 16) {
        float4 sv;
        sv.x = t0 * tv0.x + t1 * tv1.x + t2 * tv2.x;
        sv.y = t0 * tv0.y + t1 * tv1.y + t2 * tv2.y;
        sv.z = t0 * tv0.z + t1 * tv1.z + t2 * tv2.z;
        sv.w = t0 * tv0.w + t1 * tv1.w + t2 * tv2.w;
        float4 sa0 = make_float4(sv.x * av0.x, sv.y * av0.y, sv.z * av0.z, sv.w * av0.w);
        float4 sa1 = make_float4(sv.x * av1.x, sv.y * av1.y, sv.z * av1.z, sv.w * av1.w);
        stage_q(As0, r_, q_, sa0);
        stage_q(As1, r_, q_, sa1);
        *(float4*)&Bs0[bk * SMS + bc * 4] = hv0;
        *(float4*)&Bs1[bk * SMS + bc * 4] = hv1;
        __syncthreads();
        int kn = k0 + 16;
        if (kn < Ke) {
            long off = (long)(m0 + r_) * K_N + kn + q_ * 4;
            tv0 = *(const float4*)(T0 + off); tv1 = *(const float4*)(T1 + off);
            tv2 = *(const float4*)(T2 + off);
            av0 = *(const float4*)(A0 + off); av1 = *(const float4*)(A1 + off);
            hv0 = *(const float4*)&H0[(long)(kn + bk) * K_F + bc * 4];
            hv1 = *(const float4*)&H1[(long)(kn + bk) * K_F + bc * 4];
        }
        mma16(As0, Bs0, tx, ty, acc0);
        mma16(As1, Bs1, tx, ty, acc1);
        __syncthreads();
    }
    epi_store(C0, K_F, m0 + ty * 4, tx * 4, acc0, nullptr, 0.f, false);
    epi_store(C1, K_F, m0 + ty * 4, tx * 4, acc1, nullptr, 0.f, false);
}

// =============== fused q,k,v + ts projections, BM=128 (224 blocks) ===============
// grid (14, 16): x<12 -> qkv (which=x>>2, ntile=x&3); x>=12 -> ts (ntile=x-12).
__global__ void __launch_bounds__(256, 2) k_qkv_ts(
    const float* __restrict__ h, const float* __restrict__ skip,
    const float* __restrict__ qw, const float* __restrict__ kw, const float* __restrict__ vw,
    const float* __restrict__ qb, const float* __restrict__ kb, const float* __restrict__ vb,
    const float* __restrict__ l1w, const float* __restrict__ l1b,
    float* __restrict__ q, float* __restrict__ k, float* __restrict__ v,
    float* __restrict__ cat)
{
    __shared__ __align__(16) float As[16 * SMS8];
    __shared__ __align__(16) float Bs[16 * SMS];
    int x = blockIdx.x;
    int m0 = blockIdx.y * 128;
    const float *A, *W, *bb;
    float* C; int ldC, n0;
    if (x < 12) {
        int which = x >> 2; n0 = (x & 3) * 64;
        A = h;
        W = ((which == 0) ? qw : (which == 1) ? kw : vw) + (long)n0 * K_INRET;
        bb = (which == 0) ? qb : (which == 1) ? kb : vb;
        C = (which == 0) ? q : (which == 1) ? k : v;
        ldC = K_INTER;
    } else {
        n0 = (x - 12) * 64;
        A = skip;
        W = l1w + (long)n0 * K_HRET;
        bb = l1b;
        C = cat + K_OUTRET;
        ldC = K_CAT;
    }
    ull acc[4][4];
#pragma unroll
    for (int i = 0; i < 4; i++)
#pragma unroll
        for (int j = 0; j < 4; j++) acc[i][j] = 0ULL;
    loop_nt8(A + (long)m0 * K_INRET, K_INRET, W, K_INRET, K_INRET, As, Bs, acc);
    int tx = threadIdx.x & 15, ty = threadIdx.x >> 4;
    epi_store8(C, ldC, m0 + ty * 8, n0 + tx * 4, acc, bb, 0.f, false);
}

// =============== triangular masked scores, BM=128 (144 blocks) ===============
// linear tri index over (mt in [0,8), nt in [0, 2mt+2)); 72 tiles per batch.
__global__ void __launch_bounds__(256, 2) k_scores(
    const float* __restrict__ q, const float* __restrict__ k, float* __restrict__ ms)
{
    __shared__ __align__(16) float As[16 * SMS8];
    __shared__ __align__(16) float Bs[16 * SMS];
    int i = blockIdx.x;
    int mt = (int)((sqrtf(4.f * i + 1.f) - 1.f) * 0.5f);
    while (mt * mt + mt > i) mt--;
    while ((mt + 1) * (mt + 1) + (mt + 1) <= i) mt++;
    int nt = i - mt * mt - mt;
    int m0 = mt * 128, n0 = nt * 64;
    int z = blockIdx.y;
    const float* Az = q + (long)z * K_N * K_INTER + (long)m0 * K_INTER;
    const float* Bz = k + (long)z * K_N * K_INTER + (long)n0 * K_INTER;
    float* Cz = ms + (long)z * NN1;

    ull acc[4][4];
#pragma unroll
    for (int i2 = 0; i2 < 4; i2++)
#pragma unroll
        for (int j = 0; j < 4; j++) acc[i2][j] = 0ULL;
    loop_nt8(Az, K_INTER, Bz, K_INTER, K_INTER, As, Bs, acc);

    int tx = threadIdx.x & 15, ty = threadIdx.x >> 4;
#pragma unroll
    for (int i2 = 0; i2 < 4; i2++) {
        int r0i = m0 + ty * 8 + 2 * i2;
        float r0[4], r1[4];
#pragma unroll
        for (int j = 0; j < 4; j++) {
            float2 p = unpack2(acc[i2][j]);
            int col = n0 + tx * 4 + j;
            r0[j] = (r0i > col)     ? INV_GAMMA * p.x : 0.f;
            r1[j] = (r0i + 1 > col) ? INV_GAMMA * p.y : 0.f;
        }
        *(float4*)&Cz[(long)r0i * K_N + n0 + tx * 4]       = *(float4*)r0;
        *(float4*)&Cz[(long)(r0i + 1) * K_N + n0 + tx * 4] = *(float4*)r1;
    }
}

// =============== ret = ms @ v, causal K-limit, split-K x2 -> partials ===============
__global__ void __launch_bounds__(256, 3) k_ret(
    const float* __restrict__ ms, const float* __restrict__ v, float* __restrict__ P)
{
    __shared__ __align__(16) float As[16 * SMS];
    __shared__ __align__(16) float Bs[16 * SMS];
    int z = blockIdx.z;
    int b = z & 1, chunk = z >> 1;
    int m0 = blockIdx.y * 64, n0 = blockIdx.x * 64;
    int Keff = m0 + 64;
    int half = Keff >> 1;
    int Ks = chunk ? half : 0;
    int Ke = chunk ? Keff : half;
    const float* Az = ms + (long)b * NN1 + (long)m0 * K_N + Ks;
    const float* Bz = v + (long)b * K_N * K_INTER + (long)Ks * K_INTER + n0;
    float* Cz = P + (long)chunk * PHALF + (long)b * K_N * K_OUTRET;

    ull acc[2][4];
#pragma unroll
    for (int i = 0; i < 2; i++)
#pragma unroll
        for (int j = 0; j < 4; j++) acc[i][j] = 0ULL;
    loop_nn(Az, K_N, Bz, K_INTER, Ke - Ks, As, Bs, acc);

    int tx = threadIdx.x & 15, ty = threadIdx.x >> 4;
    epi_store(Cz, K_OUTRET, m0 + ty * 4, n0 + tx * 4, acc, nullptr, 0.f, false);
}

// =============== eta = PReLU((P0+P1) @ rw^T + rb) -> cat[:, :256] ===============
__global__ void __launch_bounds__(256, 3) k_eta(
    const float* __restrict__ P, const float* __restrict__ rw,
    const float* __restrict__ rb, const float* __restrict__ a_ret,
    float* __restrict__ cat)
{
    __shared__ __align__(16) float As[16 * SMS];
    __shared__ __align__(16) float Bs[16 * SMS];
    int n0 = blockIdx.x * 64, m0 = blockIdx.y * 64;
    ull acc[2][4];
#pragma unroll
    for (int i = 0; i < 2; i++)
#pragma unroll
        for (int j = 0; j < 4; j++) acc[i][j] = 0ULL;
    loop_nt<true>(P + (long)m0 * K_OUTRET, K_OUTRET,
                  P + PHALF + (long)m0 * K_OUTRET,
                  rw + (long)n0 * K_INTER, K_INTER, K_INTER, As, Bs, acc);
    int tx = threadIdx.x & 15, ty = threadIdx.x >> 4;
    epi_store(cat, K_CAT, m0 + ty * 4, n0 + tx * 4, acc, rb, *a_ret, true);
}

// ---------------- conv over relations + PReLU ----------------
__global__ void k_conv(const float* __restrict__ diff, const float* __restrict__ cw,
                       const float* __restrict__ cb, const float* __restrict__ a1,
                       int l, float* __restrict__ u) {
    const int PQ = K_N * K_F / 4;
    int i = blockIdx.x * 256 + threadIdx.x;
    if (i >= K_B * K_R * PQ) return;
    int pq = i % PQ; int s = (i / PQ) % K_R; int b = i / (PQ * K_R);
    float bb = cb[l * K_R + s];
    float4 acc = make_float4(bb, bb, bb, bb);
    const float4* d4 = (const float4*)diff;
#pragma unroll
    for (int r2 = 0; r2 < K_R; r2++) {
        float w = cw[(l * K_R + s) * K_R + r2];
        float4 v = d4[(long)(b * K_R + r2) * PQ + pq];
        acc.x += w * v.x; acc.y += w * v.y; acc.z += w * v.z; acc.w += w * v.w;
    }
    float al = a1[l];
    acc.x = (acc.x >= 0.f) ? acc.x : al * acc.x;
    acc.y = (acc.y >= 0.f) ? acc.y : al * acc.y;
    acc.z = (acc.z >= 0.f) ? acc.z : al * acc.z;
    acc.w = (acc.w >= 0.f) ? acc.w : al * acc.w;
    ((float4*)u)[i] = acc;
}

// ---------------- initial skip transpose ----------------
__global__ void k_skip0(const float* __restrict__ x, float* __restrict__ sk) {
    int i = blockIdx.x * 256 + threadIdx.x;
    if (i >= K_B * K_N * K_R * K_F) return;
    int d = i % K_F;
    int r = (i / K_F) % K_R;
    int n = (i / (K_F * K_R)) % K_N;
    int b = i / (K_F * K_R * K_N);
    sk[i] = x[(((long)b * K_R + r) * K_N + n) * K_F + d];
}

// ---------------- final tiny GEMM: out[2048,2] ----------------
__global__ void k_mlp2(const float* __restrict__ m1, const float* __restrict__ w,
                       const float* __restrict__ b, float* __restrict__ out) {
    __shared__ float ws[2 * K_H1];
    int tid = threadIdx.x;
    if (tid < 2 * K_H1) ws[tid] = w[tid];
    __syncthreads();
    int row = blockIdx.x * 256 + tid;
    const float4* mr = (const float4*)(m1 + (long)row * K_H1);
    float s0 = 0.f, s1 = 0.f;
#pragma unroll
    for (int i = 0; i < K_H1 / 4; i++) {
        float4 v = mr[i];
        s0 += v.x * ws[i * 4] + v.y * ws[i * 4 + 1] + v.z * ws[i * 4 + 2] + v.w * ws[i * 4 + 3];
        s1 += v.x * ws[K_H1 + i * 4] + v.y * ws[K_H1 + i * 4 + 1]
            + v.z * ws[K_H1 + i * 4 + 2] + v.w * ws[K_H1 + i * 4 + 3];
    }
    out[(long)row * 2]     = s0 + b[0];
    out[(long)row * 2 + 1] = s1 + b[1];
}

// ---------------- host launcher ----------------
extern "C" void kernel_launch(void* const* d_in, const int* in_sizes, int n_in,
                              void* d_out, int out_size) {
    const float* x      = (const float*)d_in[0];
    const float* a      = (const float*)d_in[1];
    const float* T      = (const float*)d_in[2];
    const float* theta  = (const float*)d_in[3];
    const float* fc_w   = (const float*)d_in[4];
    const float* fc_b   = (const float*)d_in[5];
    const float* conv_w = (const float*)d_in[6];
    const float* conv_b = (const float*)d_in[7];
    const float* a0     = (const float*)d_in[8];
    const float* a1     = (const float*)d_in[9];
    const float* qw = (const float*)d_in[10]; const float* qb = (const float*)d_in[11];
    const float* kw = (const float*)d_in[12]; const float* kb = (const float*)d_in[13];
    const float* vw = (const float*)d_in[14]; const float* vb = (const float*)d_in[15];
    const float* rw = (const float*)d_in[16]; const float* rb = (const float*)d_in[17];
    const float* a_ret = (const float*)d_in[18];
    const float* l1w = (const float*)d_in[19]; const float* l1b = (const float*)d_in[20];
    const float* l2w = (const float*)d_in[21]; const float* l2b = (const float*)d_in[22];
    const float* m1w = (const float*)d_in[23]; const float* m1b = (const float*)d_in[24];
    const float* m2w = (const float*)d_in[25]; const float* m2b = (const float*)d_in[26];
    const float* a_mlp = (const float*)d_in[27];
    float* out = (float*)d_out;

    float *P, *diff, *h, *q, *k, *v, *ms, *cat, *skA, *skB, *m1;
    cudaGetSymbolAddress((void**)&P, g_P);
    cudaGetSymbolAddress((void**)&diff, g_diff);
    cudaGetSymbolAddress((void**)&h, g_h);
    cudaGetSymbolAddress((void**)&q, g_q);
    cudaGetSymbolAddress((void**)&k, g_k);
    cudaGetSymbolAddress((void**)&v, g_v);
    cudaGetSymbolAddress((void**)&ms, g_ms);
    cudaGetSymbolAddress((void**)&cat, g_cat);
    cudaGetSymbolAddress((void**)&skA, g_skipA);
    cudaGetSymbolAddress((void**)&skB, g_skipB);
    cudaGetSymbolAddress((void**)&m1, g_m1);

    const int M2 = K_B * K_N;  // 2048

    { int tot = K_B * K_N * K_R * K_F;
      k_skip0<<<(tot + 255) / 256, 256>>>(x, skA); }

    const float* hc = x;
    float* sin_ = skA;
    float* sout = skB;

    for (int l = 0; l < 2; l++) {
        // diffusion, fused S, both batches per block, split-K x2 (160 blocks)
        k_feats<<<dim3(1, K_N / 64, K_B * K_R), 256>>>(T, theta, a, hc, P, l);

        // fc + PReLU(a0), partial reduce fused into A staging (160 blocks)
        k_gemm64<true><<<dim3(1, K_N / 64, K_B * K_R), 256>>>(
            P, P + (long)K_B * K_R * NF1,
            fc_w + (long)l * K_R * K_F * K_F, fc_b + (long)l * K_R * K_F, diff,
            K_F, K_F, NF1, K_F, (long)K_F * K_F, K_F, K_R, NF1, K_F, a0 + l);

        { int tot = K_B * K_R * K_N * K_F / 4;
          k_conv<<<(tot + 255) / 256, 256>>>(diff, conv_w, conv_b, a1, l, h); }
        hc = h;

        // fused q,k,v + ts, BM=128 (224 blocks, single wave)
        k_qkv_ts<<<dim3(14, K_N * K_B / 128), 256>>>(
            h, sin_,
            qw + (long)l * K_INTER * K_INRET, kw + (long)l * K_INTER * K_INRET,
            vw + (long)l * K_INTER * K_INRET,
            qb + (long)l * K_INTER, kb + (long)l * K_INTER, vb + (long)l * K_INTER,
            l1w + (long)l * K_H1 * K_HRET, l1b + (long)l * K_H1,
            q, k, v, cat);

        // triangular masked scores, BM=128 (144 blocks)
        k_scores<<<dim3(72, 2), 256>>>(q, k, ms);

        // ret split-K x2 -> partials in P (256 blocks)
        k_ret<<<dim3(K_OUTRET / 64, K_N / 64, 4), 256>>>(ms, v, P);

        // eta with fused partial reduce (128 blocks)
        k_eta<<<dim3(K_OUTRET / 64, M2 / 64), 256>>>(
            P, rw + (long)l * K_OUTRET * K_INTER, rb + (long)l * K_OUTRET,
            a_ret + l, cat);

        // skip' = cat @ l2^T + l2_b (160 blocks)
        k_gemm64<false><<<dim3(K_HRET / 64, M2 / 64, 1), 256>>>(
            cat, nullptr, l2w + (long)l * K_HRET * K_CAT, l2b + (long)l * K_HRET, sout,
            K_HRET, K_CAT, 0, K_CAT, 0, K_CAT, 1, 0, K_HRET, nullptr);

        float* t0 = sin_; sin_ = sout; sout = t0;
    }

    // final MLP
    k_gemm64<false><<<dim3(K_H1 / 64, M2 / 64, 1), 256>>>(
        sin_, nullptr, m1w, m1b, m1,
        K_H1, K_HRET, 0, K_HRET, 0, K_HRET, 1, 0, K_H1, a_mlp);
    k_mlp2<<<M2 / 256, 256>>>(m1, m2w, m2b, out);
}